// round 3
// baseline (speedup 1.0000x reference)
#include <cuda_runtime.h>

#define L_TOTAL 32768
#define KQ      1024
#define EDIM    64
#define LTILE   64      // latents per block
#define KCH     64      // codes per staged chunk
#define CT      8       // threads along codes  (TN=8 codes each)
#define LT      16      // threads along latents (TM=4 latents each)
#define TM      4
#define TN      8
#define THREADS 128

// scratch (no cudaMalloc allowed)
__device__ float g_c[KQ];               // ||e_k||^2
__device__ float g_eT[EDIM * KQ];       // transposed embeddings eT[e][k]

__device__ __forceinline__ unsigned long long pk2(float a, float b) {
    unsigned long long r;
    asm("mov.b64 %0, {%1, %2};" : "=l"(r) : "f"(a), "f"(b));
    return r;
}
__device__ __forceinline__ void upk2(unsigned long long v, float& a, float& b) {
    asm("mov.b64 {%0, %1}, %2;" : "=f"(a), "=f"(b) : "l"(v));
}
__device__ __forceinline__ unsigned long long fma2(unsigned long long a,
                                                   unsigned long long b,
                                                   unsigned long long c) {
    unsigned long long d;
    asm("fma.rn.f32x2 %0, %1, %2, %3;" : "=l"(d) : "l"(a), "l"(b), "l"(c));
    return d;
}

// Prep: ||e_k||^2 and transposed embedding table (coalesced writes).
__global__ void vq_prep_kernel(const float* __restrict__ emb) {
    int k = blockIdx.x * blockDim.x + threadIdx.x;   // 0..1023 exact
    const float4* row = reinterpret_cast<const float4*>(emb + k * EDIM);
    float s = 0.f;
    #pragma unroll
    for (int i = 0; i < EDIM / 4; i++) {
        float4 v = row[i];
        s += v.x * v.x + v.y * v.y + v.z * v.z + v.w * v.w;
        g_eT[(4 * i + 0) * KQ + k] = v.x;
        g_eT[(4 * i + 1) * KQ + k] = v.y;
        g_eT[(4 * i + 2) * KQ + k] = v.z;
        g_eT[(4 * i + 3) * KQ + k] = v.w;
    }
    g_c[k] = s;
}

__global__ void __launch_bounds__(THREADS, 4)
vq_main_kernel(const float* __restrict__ x,
               const float* __restrict__ emb,
               float* __restrict__ out) {
    __shared__ float sx[EDIM * LTILE];   // transposed x tile: sx[e][l]
    __shared__ float se[EDIM * KCH];     // transposed code chunk: se[e][c]
    __shared__ int   sidx[LTILE];

    const int tid   = threadIdx.x;
    const int ct    = tid & (CT - 1);    // code group
    const int lt    = tid >> 3;          // latent group
    const int lbase = blockIdx.x * LTILE;

    // Stage x tile transposed (once per block). Coalesced float4 reads.
    #pragma unroll
    for (int i = 0; i < 8; i++) {
        int idx = tid + i * THREADS;     // 0..1023
        int l   = idx >> 4;              // 0..63
        int e4  = idx & 15;              // float4 index along e
        float4 v = reinterpret_cast<const float4*>(x)[(size_t)(lbase + l) * 16 + e4];
        sx[(4 * e4 + 0) * LTILE + l] = v.x;
        sx[(4 * e4 + 1) * LTILE + l] = v.y;
        sx[(4 * e4 + 2) * LTILE + l] = v.z;
        sx[(4 * e4 + 3) * LTILE + l] = v.w;
    }

    float best[TM];
    int   bidx[TM];
    #pragma unroll
    for (int m = 0; m < TM; m++) { best[m] = 3.4e38f; bidx[m] = 0; }

    for (int c0 = 0; c0 < KQ; c0 += KCH) {
        __syncthreads();   // previous chunk consumed (also covers sx staging)
        // Stage code chunk from pre-transposed table (fully coalesced).
        #pragma unroll
        for (int i = 0; i < 8; i++) {
            int idx = tid + i * THREADS;
            int e   = idx >> 4;
            int c4  = idx & 15;
            reinterpret_cast<float4*>(se)[e * 16 + c4] =
                *reinterpret_cast<const float4*>(&g_eT[e * KQ + c0 + 4 * c4]);
        }
        __syncthreads();

        unsigned long long acc[TM][TN / 2];
        #pragma unroll
        for (int m = 0; m < TM; m++)
            #pragma unroll
            for (int j = 0; j < TN / 2; j++) acc[m][j] = 0ull;

        #pragma unroll 4
        for (int e = 0; e < EDIM; e++) {
            float4 xv = *reinterpret_cast<const float4*>(&sx[e * LTILE + 4 * lt]);
            const unsigned long long* eu =
                reinterpret_cast<const unsigned long long*>(&se[e * KCH + 8 * ct]);
            unsigned long long e0 = eu[0], e1 = eu[1], e2 = eu[2], e3 = eu[3];
            unsigned long long xm;
            xm = pk2(xv.x, xv.x);
            acc[0][0] = fma2(xm, e0, acc[0][0]);
            acc[0][1] = fma2(xm, e1, acc[0][1]);
            acc[0][2] = fma2(xm, e2, acc[0][2]);
            acc[0][3] = fma2(xm, e3, acc[0][3]);
            xm = pk2(xv.y, xv.y);
            acc[1][0] = fma2(xm, e0, acc[1][0]);
            acc[1][1] = fma2(xm, e1, acc[1][1]);
            acc[1][2] = fma2(xm, e2, acc[1][2]);
            acc[1][3] = fma2(xm, e3, acc[1][3]);
            xm = pk2(xv.z, xv.z);
            acc[2][0] = fma2(xm, e0, acc[2][0]);
            acc[2][1] = fma2(xm, e1, acc[2][1]);
            acc[2][2] = fma2(xm, e2, acc[2][2]);
            acc[2][3] = fma2(xm, e3, acc[2][3]);
            xm = pk2(xv.w, xv.w);
            acc[3][0] = fma2(xm, e0, acc[3][0]);
            acc[3][1] = fma2(xm, e1, acc[3][1]);
            acc[3][2] = fma2(xm, e2, acc[3][2]);
            acc[3][3] = fma2(xm, e3, acc[3][3]);
        }

        // Scores + running argmin (codes ascending, strict < => first-min).
        #pragma unroll
        for (int m = 0; m < TM; m++) {
            #pragma unroll
            for (int j = 0; j < TN / 2; j++) {
                float lo, hi;
                upk2(acc[m][j], lo, hi);
                int k0 = c0 + 8 * ct + 2 * j;
                float s0 = fmaf(-2.0f, lo, __ldg(&g_c[k0]));
                float s1 = fmaf(-2.0f, hi, __ldg(&g_c[k0 + 1]));
                if (s0 < best[m]) { best[m] = s0; bidx[m] = k0; }
                if (s1 < best[m]) { best[m] = s1; bidx[m] = k0 + 1; }
            }
        }
    }

    // Reduce across the 8 code-groups (lanes ct=0..7 within each lt group).
    #pragma unroll
    for (int m = 0; m < TM; m++) {
        #pragma unroll
        for (int d = 1; d < CT; d <<= 1) {
            float ob = __shfl_xor_sync(0xffffffffu, best[m], d);
            int   oi = __shfl_xor_sync(0xffffffffu, bidx[m], d);
            if (ob < best[m] || (ob == best[m] && oi < bidx[m])) {
                best[m] = ob; bidx[m] = oi;
            }
        }
    }
    if (ct == 0) {
        #pragma unroll
        for (int m = 0; m < TM; m++) sidx[4 * lt + m] = bidx[m];
    }
    __syncthreads();

    // Coalesced epilogue: out = [x | quantized | z_hat | indices], all fp32.
    const size_t LE4 = (size_t)L_TOTAL * (EDIM / 4);
    const float4* x4 = reinterpret_cast<const float4*>(x);
    const float4* e4p = reinterpret_cast<const float4*>(emb);
    float4* out4 = reinterpret_cast<float4*>(out);
    #pragma unroll
    for (int i = 0; i < 8; i++) {
        int idx = tid + i * THREADS;     // 0..1023
        int l   = idx >> 4;
        int c4  = idx & 15;
        size_t goff = (size_t)(lbase + l) * 16 + c4;
        float4 xv = x4[goff];
        float4 qv = e4p[(size_t)sidx[l] * 16 + c4];
        out4[goff] = xv;
        out4[LE4 + goff] = qv;
        float4 zh;
        zh.x = (xv.x + qv.x) - xv.x;
        zh.y = (xv.y + qv.y) - xv.y;
        zh.z = (xv.z + qv.z) - xv.z;
        zh.w = (xv.w + qv.w) - xv.w;
        out4[2 * LE4 + goff] = zh;
    }
    if (tid < LTILE)
        out[3 * (size_t)L_TOTAL * EDIM + lbase + tid] = (float)sidx[tid];
}

extern "C" void kernel_launch(void* const* d_in, const int* in_sizes, int n_in,
                              void* d_out, int out_size) {
    const float* x   = (const float*)d_in[0];
    const float* emb = (const float*)d_in[1];
    float* out       = (float*)d_out;

    vq_prep_kernel<<<KQ / 256, 256>>>(emb);
    vq_main_kernel<<<L_TOTAL / LTILE, THREADS>>>(x, emb, out);
}

// round 5
// speedup vs baseline: 2.1216x; 2.1216x over previous
#include <cuda_runtime.h>
#include <cuda_fp16.h>

#define L_TOTAL 32768
#define KQ      1024
#define EDIM    64
#define MT      64             // latents per CTA (4 warps x 16)
#define CHK     64             // codes per staged chunk
#define SROW    72             // padded smem row stride (halves) -> conflict-free
#define THREADS 128

// scratch tables (no cudaMalloc allowed)
__device__ float  g_c[KQ];             // ||e_k||^2 (fp32)
__device__ __half g_ehi[KQ * EDIM];    // fp16-rounded embeddings [k][e]
__device__ __half g_elo[KQ * EDIM];    // residual

__device__ __forceinline__ void mma16816(float* d, const unsigned* a,
                                         unsigned b0, unsigned b1) {
    asm volatile(
        "mma.sync.aligned.m16n8k16.row.col.f32.f16.f16.f32 "
        "{%0,%1,%2,%3}, {%4,%5,%6,%7}, {%8,%9}, {%0,%1,%2,%3};"
        : "+f"(d[0]), "+f"(d[1]), "+f"(d[2]), "+f"(d[3])
        : "r"(a[0]), "r"(a[1]), "r"(a[2]), "r"(a[3]), "r"(b0), "r"(b1));
}

__device__ __forceinline__ unsigned packsplit(float a, float b, unsigned& lo) {
    __half ha = __float2half_rn(a), hb = __float2half_rn(b);
    float la = a - __half2float(ha), lb = b - __half2float(hb);
    __half2 H = __halves2half2(ha, hb);
    __half2 L = __halves2half2(__float2half_rn(la), __float2half_rn(lb));
    lo = *reinterpret_cast<unsigned*>(&L);
    return *reinterpret_cast<unsigned*>(&H);
}

// Prep: ||e||^2 (fp32) + fp16 hi/lo split tables.
__global__ void vq_prep_kernel(const float* __restrict__ emb) {
    int k = blockIdx.x * blockDim.x + threadIdx.x;   // 0..1023 exact
    const float2* row = reinterpret_cast<const float2*>(emb + k * EDIM);
    float s = 0.f;
    #pragma unroll
    for (int i = 0; i < EDIM / 2; i++) {
        float2 v = row[i];
        s += v.x * v.x + v.y * v.y;
        unsigned lo, hi = packsplit(v.x, v.y, lo);
        *reinterpret_cast<unsigned*>(&g_ehi[k * EDIM + 2 * i]) = hi;
        *reinterpret_cast<unsigned*>(&g_elo[k * EDIM + 2 * i]) = lo;
    }
    g_c[k] = s;
}

struct Top2 { float b1, b2; int i1, i2; };

__device__ __forceinline__ void upd(Top2& t, float s, int c) {
    if (s < t.b1)      { t.b2 = t.b1; t.i2 = t.i1; t.b1 = s; t.i1 = c; }
    else if (s < t.b2) { t.b2 = s; t.i2 = c; }
}

__global__ void __launch_bounds__(THREADS)
vq_mma_kernel(const float* __restrict__ x,
              const float* __restrict__ emb,
              float* __restrict__ out) {
    __shared__ __align__(16) __half sBhi[CHK * SROW];
    __shared__ __align__(16) __half sBlo[CHK * SROW];
    __shared__ float cs[KQ];
    __shared__ int   sidx[MT];

    const int tid   = threadIdx.x;
    const int warp  = tid >> 5;
    const int lane  = tid & 31;
    const int g     = lane >> 2;       // group id (row within tile)
    const int T     = lane & 3;        // thread in group
    const int lbase = blockIdx.x * MT;

    // stage ||e||^2
    #pragma unroll
    for (int i = 0; i < KQ / THREADS; i++)
        cs[tid + i * THREADS] = g_c[tid + i * THREADS];

    // A fragments: rows r0 = warp*16+g, r1 = r0+8 of (-2x), hi/lo split.
    unsigned ahi[4][4], alo[4][4];
    {
        const float* xr0 = x + (size_t)(lbase + warp * 16 + g) * EDIM;
        const float* xr1 = xr0 + 8 * EDIM;
        #pragma unroll
        for (int ks = 0; ks < 4; ks++) {
            int c0 = 16 * ks + 2 * T;
            float2 v;
            v = *reinterpret_cast<const float2*>(xr0 + c0);
            ahi[ks][0] = packsplit(-2.f * v.x, -2.f * v.y, alo[ks][0]);
            v = *reinterpret_cast<const float2*>(xr1 + c0);
            ahi[ks][1] = packsplit(-2.f * v.x, -2.f * v.y, alo[ks][1]);
            v = *reinterpret_cast<const float2*>(xr0 + c0 + 8);
            ahi[ks][2] = packsplit(-2.f * v.x, -2.f * v.y, alo[ks][2]);
            v = *reinterpret_cast<const float2*>(xr1 + c0 + 8);
            ahi[ks][3] = packsplit(-2.f * v.x, -2.f * v.y, alo[ks][3]);
        }
    }

    Top2 tp[2];
    tp[0].b1 = tp[0].b2 = 3.4e38f; tp[0].i1 = tp[0].i2 = 0;
    tp[1].b1 = tp[1].b2 = 3.4e38f; tp[1].i1 = tp[1].i2 = 0;

    #pragma unroll 1
    for (int ch = 0; ch < KQ / CHK; ch++) {
        const int c0 = ch * CHK;
        __syncthreads();   // previous chunk consumed
        // Stage 64 codes (hi+lo) with padded stride. Coalesced 16B moves.
        #pragma unroll
        for (int i = 0; i < (CHK * 8) / THREADS; i++) {
            int u = tid + i * THREADS;
            int row = u >> 3, seg = u & 7;
            *reinterpret_cast<float4*>(&sBhi[row * SROW + seg * 8]) =
                *reinterpret_cast<const float4*>(&g_ehi[(size_t)(c0 + row) * EDIM + seg * 8]);
            *reinterpret_cast<float4*>(&sBlo[row * SROW + seg * 8]) =
                *reinterpret_cast<const float4*>(&g_elo[(size_t)(c0 + row) * EDIM + seg * 8]);
        }
        __syncthreads();

        #pragma unroll
        for (int nb = 0; nb < CHK; nb += 16) {
            float d[2][4] = {{0.f, 0.f, 0.f, 0.f}, {0.f, 0.f, 0.f, 0.f}};
            #pragma unroll
            for (int j = 0; j < 2; j++) {
                const int nrow = nb + 8 * j + g;
                const __half* ph = &sBhi[nrow * SROW + 2 * T];
                const __half* pl = &sBlo[nrow * SROW + 2 * T];
                #pragma unroll
                for (int kh = 0; kh < 2; kh++) {  // k halves 0..31, 32..63
                    int off = kh * 32;
                    unsigned h0 = *reinterpret_cast<const unsigned*>(ph + off);
                    unsigned h1 = *reinterpret_cast<const unsigned*>(ph + off + 8);
                    unsigned h2 = *reinterpret_cast<const unsigned*>(ph + off + 16);
                    unsigned h3 = *reinterpret_cast<const unsigned*>(ph + off + 24);
                    unsigned l0 = *reinterpret_cast<const unsigned*>(pl + off);
                    unsigned l1 = *reinterpret_cast<const unsigned*>(pl + off + 8);
                    unsigned l2 = *reinterpret_cast<const unsigned*>(pl + off + 16);
                    unsigned l3 = *reinterpret_cast<const unsigned*>(pl + off + 24);
                    int ks = 2 * kh;
                    mma16816(d[j], ahi[ks], h0, h1);      // hi*hi
                    mma16816(d[j], ahi[ks], l0, l1);      // hi*lo
                    mma16816(d[j], alo[ks], h0, h1);      // lo*hi
                    mma16816(d[j], ahi[ks + 1], h2, h3);
                    mma16816(d[j], ahi[ks + 1], l2, l3);
                    mma16816(d[j], alo[ks + 1], h2, h3);
                }
            }
            // scores = ||e||^2 + (-2x)·e ; D cols = nb+8j+2T,+1; rows g, g+8
            #pragma unroll
            for (int j = 0; j < 2; j++) {
                int col = c0 + nb + 8 * j + 2 * T;
                float e0 = cs[col], e1 = cs[col + 1];
                upd(tp[0], e0 + d[j][0], col);
                upd(tp[0], e1 + d[j][1], col + 1);
                upd(tp[1], e0 + d[j][2], col);
                upd(tp[1], e1 + d[j][3], col + 1);
            }
        }
    }

    // Reduce across the 4 lanes of each group (xor 1, 2 stay in-quad).
    #pragma unroll
    for (int s = 0; s < 2; s++) {
        #pragma unroll
        for (int m = 1; m < 4; m <<= 1) {
            float ob1 = __shfl_xor_sync(0xffffffffu, tp[s].b1, m);
            float ob2 = __shfl_xor_sync(0xffffffffu, tp[s].b2, m);
            int   oi1 = __shfl_xor_sync(0xffffffffu, tp[s].i1, m);
            int   oi2 = __shfl_xor_sync(0xffffffffu, tp[s].i2, m);
            bool of = (ob1 < tp[s].b1) || (ob1 == tp[s].b1 && oi1 < tp[s].i1);
            if (of) {
                bool t2 = (tp[s].b1 < ob2) || (tp[s].b1 == ob2 && tp[s].i1 < oi2);
                tp[s].b2 = t2 ? tp[s].b1 : ob2;
                tp[s].i2 = t2 ? tp[s].i1 : oi2;
                tp[s].b1 = ob1; tp[s].i1 = oi1;
            } else {
                bool t2 = (ob1 < tp[s].b2) || (ob1 == tp[s].b2 && oi1 < tp[s].i2);
                if (t2) { tp[s].b2 = ob1; tp[s].i2 = oi1; }
            }
        }
    }

    if (T == 0) {
        #pragma unroll
        for (int s = 0; s < 2; s++) {
            int win = tp[s].i1;
            if (tp[s].b2 - tp[s].b1 < 5e-3f) {
                // exact fp32 recheck of the two candidates
                int gl = lbase + warp * 16 + g + 8 * s;
                const float* xr  = x   + (size_t)gl * EDIM;
                const float* e1r = emb + (size_t)tp[s].i1 * EDIM;
                const float* e2r = emb + (size_t)tp[s].i2 * EDIM;
                float d1 = 0.f, d2 = 0.f;
                #pragma unroll 8
                for (int e = 0; e < EDIM; e++) {
                    float xv = xr[e];
                    d1 = fmaf(xv, e1r[e], d1);
                    d2 = fmaf(xv, e2r[e], d2);
                }
                float s1 = fmaf(-2.f, d1, cs[tp[s].i1]);
                float s2 = fmaf(-2.f, d2, cs[tp[s].i2]);
                if (s2 < s1 || (s2 == s1 && tp[s].i2 < tp[s].i1)) win = tp[s].i2;
            }
            sidx[warp * 16 + g + 8 * s] = win;
        }
    }
    __syncthreads();

    // Coalesced epilogue: out = [x | quantized | z_hat | indices], fp32.
    const size_t LE4 = (size_t)L_TOTAL * (EDIM / 4);
    const float4* x4  = reinterpret_cast<const float4*>(x);
    const float4* e4p = reinterpret_cast<const float4*>(emb);
    float4* out4 = reinterpret_cast<float4*>(out);
    #pragma unroll
    for (int i = 0; i < (MT * EDIM / 4) / THREADS; i++) {
        int idx = tid + i * THREADS;
        int l = idx >> 4, c4 = idx & 15;
        size_t goff = (size_t)(lbase + l) * 16 + c4;
        float4 xv = x4[goff];
        float4 qv = e4p[(size_t)sidx[l] * 16 + c4];
        out4[goff] = xv;
        out4[LE4 + goff] = qv;
        float4 zh;
        zh.x = (xv.x + qv.x) - xv.x;
        zh.y = (xv.y + qv.y) - xv.y;
        zh.z = (xv.z + qv.z) - xv.z;
        zh.w = (xv.w + qv.w) - xv.w;
        out4[2 * LE4 + goff] = zh;
    }
    if (tid < MT)
        out[3 * (size_t)L_TOTAL * EDIM + lbase + tid] = (float)sidx[tid];
}

extern "C" void kernel_launch(void* const* d_in, const int* in_sizes, int n_in,
                              void* d_out, int out_size) {
    const float* x   = (const float*)d_in[0];
    const float* emb = (const float*)d_in[1];
    float* out       = (float*)d_out;

    vq_prep_kernel<<<KQ / 256, 256>>>(emb);
    vq_mma_kernel<<<L_TOTAL / MT, THREADS>>>(x, emb, out);
}